// round 5
// baseline (speedup 1.0000x reference)
#include <cuda_runtime.h>
#include <cstdint>
#include <math.h>

// Problem dims
#define B_   512
#define T_   512
#define IN_  128
#define H_   256
#define G3_  768   // 3*H
#define OUT_ 128

// Scratch (device globals — allocation inside kernel_launch is forbidden).
__device__ float g_ig[(size_t)B_ * T_ * G3_];     // ~805 MB  [B][T][3H]
__device__ float g_hfin[(size_t)B_ * H_];

typedef unsigned long long ull;

// ---------------- packed fp32 helpers (Blackwell f32x2) --------------------
__device__ __forceinline__ ull pk2(float lo, float hi) {
    ull r;
    asm("mov.b64 %0, {%1, %2};" : "=l"(r) : "f"(lo), "f"(hi));
    return r;
}
__device__ __forceinline__ void fma2(ull& d, ull a, ull b) {
    asm("fma.rn.f32x2 %0, %1, %2, %0;" : "+l"(d) : "l"(a), "l"(b));
}
__device__ __forceinline__ float2 upk(ull v) {
    float2 f;
    asm("mov.b64 {%0, %1}, %2;" : "=f"(f.x), "=f"(f.y) : "l"(v));
    return f;
}

// ---------------------------------------------------------------------------
// Phase 1: ig = X @ W_ih^T + bias   (M=262144, N=768, K=128)
// 128x128 tile, full K resident in smem, 8x8 outputs/thread, f32x2 FMAs.
// B tile stored DUPLICATED ([k][2n]=[k][2n+1]=w) so the broadcast operand is
// loaded as a ready-packed f32x2 pair -> no packing MOVs in the inner loop.
// ---------------------------------------------------------------------------
#define SA_STRIDE 132                       // pad: keeps 16B align (132*4=528%16==0... see note)
#define P1_SMEM_FLOATS (128 * SA_STRIDE + 128 * 256)
#define P1_SMEM_BYTES  (P1_SMEM_FLOATS * 4)   // 198656 B

__global__ void __launch_bounds__(256, 1) k_ih(const float* __restrict__ X,
                                               const float* __restrict__ W,
                                               const float* __restrict__ bias)
{
    extern __shared__ float sm1[];
    float* sA = sm1;                        // [k][m]  stride SA_STRIDE
    float* sB = sm1 + 128 * SA_STRIDE;      // [k][2n] duplicated, stride 256

    const int tid = threadIdx.x;
    const int bm = blockIdx.x, bn = blockIdx.y;

    // ---- stage A (transpose) and B (transpose + duplicate) ----
    {
        const int row   = tid >> 1;          // 0..127
        const int khalf = (tid & 1) * 64;
        const float* xs = X + ((size_t)(bm * 128 + row)) * 128 + khalf;
        const float* ws = W + ((size_t)(bn * 128 + row)) * 128 + khalf;
#pragma unroll
        for (int q = 0; q < 16; q++) {
            const float4 xv = *(const float4*)(xs + q * 4);
            const float4 wv = *(const float4*)(ws + q * 4);
            const int k0 = khalf + q * 4;
            sA[(k0 + 0) * SA_STRIDE + row] = xv.x;
            sA[(k0 + 1) * SA_STRIDE + row] = xv.y;
            sA[(k0 + 2) * SA_STRIDE + row] = xv.z;
            sA[(k0 + 3) * SA_STRIDE + row] = xv.w;
            *(float2*)(sB + (k0 + 0) * 256 + 2 * row) = make_float2(wv.x, wv.x);
            *(float2*)(sB + (k0 + 1) * 256 + 2 * row) = make_float2(wv.y, wv.y);
            *(float2*)(sB + (k0 + 2) * 256 + 2 * row) = make_float2(wv.z, wv.z);
            *(float2*)(sB + (k0 + 3) * 256 + 2 * row) = make_float2(wv.w, wv.w);
        }
    }
    __syncthreads();

    const int ty = tid >> 4, tx = tid & 15;   // 16x16 thread grid
    const float* aBase = sA + ty * 8;
    const float* bBase = sB + tx * 16;

    ull acc[4][8];
#pragma unroll
    for (int i = 0; i < 4; i++)
#pragma unroll
        for (int j = 0; j < 8; j++) acc[i][j] = 0ULL;

#pragma unroll 4
    for (int k = 0; k < 128; k++) {
        // a-pairs: 8 consecutive m as 4 packed f32x2 (2 x LDS.128)
        const ulonglong2 aL = *(const ulonglong2*)(aBase + k * SA_STRIDE);
        const ulonglong2 aH = *(const ulonglong2*)(aBase + k * SA_STRIDE + 4);
        // b duplicated pairs: 8 n-values (4 x LDS.128)
        const ulonglong2 b0 = *(const ulonglong2*)(bBase + k * 256);
        const ulonglong2 b1 = *(const ulonglong2*)(bBase + k * 256 + 4);
        const ulonglong2 b2 = *(const ulonglong2*)(bBase + k * 256 + 8);
        const ulonglong2 b3 = *(const ulonglong2*)(bBase + k * 256 + 12);
        const ull ap[4] = {aL.x, aL.y, aH.x, aH.y};
        const ull bd[8] = {b0.x, b0.y, b1.x, b1.y, b2.x, b2.y, b3.x, b3.y};
#pragma unroll
        for (int i = 0; i < 4; i++)
#pragma unroll
            for (int j = 0; j < 8; j++)
                fma2(acc[i][j], ap[i], bd[j]);
    }

    // epilogue: acc[i][j] = rows (ty*8+2i, ty*8+2i+1), col tx*8+j
    const float4 bb0 = *(const float4*)(bias + bn * 128 + tx * 8);
    const float4 bb1 = *(const float4*)(bias + bn * 128 + tx * 8 + 4);
#pragma unroll
    for (int i = 0; i < 4; i++) {
        float2 c[8];
#pragma unroll
        for (int j = 0; j < 8; j++) c[j] = upk(acc[i][j]);
        float* r0 = g_ig + ((size_t)(bm * 128 + ty * 8 + 2 * i)) * G3_ + bn * 128 + tx * 8;
        float* r1 = r0 + G3_;
        *(float4*)(r0)     = make_float4(c[0].x + bb0.x, c[1].x + bb0.y, c[2].x + bb0.z, c[3].x + bb0.w);
        *(float4*)(r0 + 4) = make_float4(c[4].x + bb1.x, c[5].x + bb1.y, c[6].x + bb1.z, c[7].x + bb1.w);
        *(float4*)(r1)     = make_float4(c[0].y + bb0.x, c[1].y + bb0.y, c[2].y + bb0.z, c[3].y + bb0.w);
        *(float4*)(r1 + 4) = make_float4(c[4].y + bb1.x, c[5].y + bb1.y, c[6].y + bb1.z, c[7].y + bb1.w);
    }
}

// ---------------------------------------------------------------------------
// Phase 2: GRU recurrence. Cluster of 4 CTAs; rank c owns 64 hidden units with
// its W_hh chunk smem-resident (192 KB). Cluster handles 16 batch rows.
// 128 threads = 64 units x 2 rowgroups (8 rows each): per k only
// 3 w-LDS + 4 h-LDS.64 + 3 packs + 12 FFMA2 -> fma-pipe bound.
// h double-buffered as float2[rowpair][unit]; exchanged via DSMEM stores.
// ---------------------------------------------------------------------------
__device__ __forceinline__ uint32_t smem_u32(const void* p) {
    uint32_t a;
    asm("{ .reg .u64 t; cvta.to.shared.u64 t, %1; cvt.u32.u64 %0, t; }" : "=r"(a) : "l"(p));
    return a;
}
__device__ __forceinline__ uint32_t mapa_u32(uint32_t a, uint32_t rank) {
    uint32_t r;
    asm("mapa.shared::cluster.u32 %0, %1, %2;" : "=r"(r) : "r"(a), "r"(rank));
    return r;
}
__device__ __forceinline__ void stc_b64(uint32_t a, ull v) {
    asm volatile("st.shared::cluster.b64 [%0], %1;" :: "r"(a), "l"(v) : "memory");
}
__device__ __forceinline__ void cluster_sync_() {
    asm volatile("barrier.cluster.arrive.aligned;" ::: "memory");
    asm volatile("barrier.cluster.wait.aligned;"   ::: "memory");
}
__device__ __forceinline__ float gru_cell(float igr, float igz, float ign,
                                          float ar, float az, float an,
                                          float bnv, float hp) {
    float r = __fdividef(1.f, 1.f + __expf(-(igr + ar)));
    float z = __fdividef(1.f, 1.f + __expf(-(igz + az)));
    float n = tanhf(ign + r * (an + bnv));
    return n + z * (hp - n);
}

// smem: sW 3*256*64 floats (192KB) + 2 x h buffers (8 rowpairs x 256 units float2)
#define REC_SMEM_BYTES ((3 * 256 * 64 + 2 * 8 * 256 * 2) * 4)   // 229376 B

__global__ void __launch_bounds__(128, 1) __cluster_dims__(4, 1, 1)
k_rec(const float* __restrict__ Whh, const float* __restrict__ bn)
{
    extern __shared__ float sm[];
    float*  sW  = sm;                         // [gate][k][unit] : 3*256*64
    float2* sH0 = (float2*)(sm + 49152);      // [rowpair(8)][unit(256)]
    float2* sH1 = (float2*)(sm + 53248);

    const int tid = threadIdx.x;
    const int c   = blockIdx.x & 3;   // cluster rank (unit chunk)
    const int cl  = blockIdx.x >> 2;  // cluster id: batch rows [cl*16, cl*16+16)

    // Stage W_hh chunk, transposed to unit-contiguous layout
    for (int flat = tid; flat < 3 * 64 * 64; flat += 128) {
        const int kv  = flat / 192;
        const int rem = flat - kv * 192;
        const int g   = rem >> 6;
        const int uu  = rem & 63;
        const float4 v = *(const float4*)(Whh + ((size_t)(g * 256 + c * 64 + uu)) * 256 + kv * 4);
        float* d = sW + (g * 256 + kv * 4) * 64 + uu;
        d[0] = v.x; d[64] = v.y; d[128] = v.z; d[192] = v.w;
    }
    for (int i = tid; i < 2048; i += 128) sH0[i] = make_float2(0.f, 0.f);  // h_0 = 0
    __syncthreads();
    cluster_sync_();  // peers' smem initialized before any remote store

    const int u   = tid & 63;         // unit within chunk
    const int rg  = tid >> 6;         // rowgroup 0/1 (8 rows each)
    const int gu  = c * 64 + u;       // global hidden-unit index
    const int rp0 = rg * 4;           // rowpairs rp0..rp0+3
    const int b0  = cl * 16 + rg * 8; // first global batch row of this thread

    const float bnv = bn[gu];

    const uint32_t a0 = smem_u32(sH0), a1 = smem_u32(sH1);
    uint32_t p0[4], p1[4];
#pragma unroll
    for (int r = 0; r < 4; r++) { p0[r] = mapa_u32(a0, r); p1[r] = mapa_u32(a1, r); }

    const float* wr = sW + u;
    const float* wz = sW + 256 * 64 + u;
    const float* wn = sW + 512 * 64 + u;

    const size_t rstr = (size_t)T_ * G3_;   // batch-row stride in g_ig
    const float* igb = g_ig + (size_t)b0 * rstr + gu;

    uint32_t off[4];
#pragma unroll
    for (int x = 0; x < 4; x++) off[x] = (uint32_t)(((rp0 + x) * 256 + gu) * 8);

    for (int t = 0; t < T_; t++) {
        const float2*   sHc   = (t & 1) ? sH1 : sH0;
        const uint32_t* pnext = (t & 1) ? p0 : p1;

        // prefetch input gates for this step's 8 rows (consumed ~6K cycles later)
        const size_t tb = (size_t)t * G3_;
        float igr[8], igz[8], ign[8];
#pragma unroll
        for (int j = 0; j < 8; j++) {
            const float* p = igb + (size_t)j * rstr + tb;
            igr[j] = p[0]; igz[j] = p[256]; ign[j] = p[512];
        }

        ull aR[4] = {0ULL, 0ULL, 0ULL, 0ULL};
        ull aZ[4] = {0ULL, 0ULL, 0ULL, 0ULL};
        ull aN[4] = {0ULL, 0ULL, 0ULL, 0ULL};

        const ull* hb0 = (const ull*)sHc + (rp0 + 0) * 256;
        const ull* hb1 = (const ull*)sHc + (rp0 + 1) * 256;
        const ull* hb2 = (const ull*)sHc + (rp0 + 2) * 256;
        const ull* hb3 = (const ull*)sHc + (rp0 + 3) * 256;

#pragma unroll 8
        for (int k = 0; k < 256; k++) {
            const float w0 = wr[k * 64];
            const float w1 = wz[k * 64];
            const float w2 = wn[k * 64];
            const ull h0 = hb0[k];   // broadcast within warp (rg fixed)
            const ull h1 = hb1[k];
            const ull h2 = hb2[k];
            const ull h3 = hb3[k];
            const ull w02 = pk2(w0, w0);
            const ull w12 = pk2(w1, w1);
            const ull w22 = pk2(w2, w2);
            fma2(aR[0], w02, h0); fma2(aR[1], w02, h1); fma2(aR[2], w02, h2); fma2(aR[3], w02, h3);
            fma2(aZ[0], w12, h0); fma2(aZ[1], w12, h1); fma2(aZ[2], w12, h2); fma2(aZ[3], w12, h3);
            fma2(aN[0], w22, h0); fma2(aN[1], w22, h1); fma2(aN[2], w22, h2); fma2(aN[3], w22, h3);
        }

        // previous h for own unit (4 rowpairs = 8 rows)
        float2 hp[4];
#pragma unroll
        for (int x = 0; x < 4; x++) hp[x] = sHc[(rp0 + x) * 256 + gu];

        ull hn[4];
#pragma unroll
        for (int x = 0; x < 4; x++) {
            const float2 ar = upk(aR[x]);
            const float2 az = upk(aZ[x]);
            const float2 an = upk(aN[x]);
            const float hx = gru_cell(igr[2*x],   igz[2*x],   ign[2*x],   ar.x, az.x, an.x, bnv, hp[x].x);
            const float hy = gru_cell(igr[2*x+1], igz[2*x+1], ign[2*x+1], ar.y, az.y, an.y, bnv, hp[x].y);
            hn[x] = pk2(hx, hy);
        }

#pragma unroll
        for (int r = 0; r < 4; r++) {
            const uint32_t base = pnext[r];
            stc_b64(base + off[0], hn[0]);
            stc_b64(base + off[1], hn[1]);
            stc_b64(base + off[2], hn[2]);
            stc_b64(base + off[3], hn[3]);
        }
        cluster_sync_();  // release stores / acquire for next step's reads
    }

    // T_ even -> final h lives in sH0
    for (int i = tid; i < 8 * 64; i += 128) {
        const int rp = i >> 6, uu = i & 63;
        const float2 v = sH0[rp * 256 + c * 64 + uu];
        float* d = g_hfin + (size_t)(cl * 16 + rp * 2) * H_ + c * 64 + uu;
        d[0]  = v.x;
        d[H_] = v.y;
    }
}

// ---------------------------------------------------------------------------
// Phase 3: out = h_final @ w_lin^T + bias_out   (512 x 128, trivial)
// ---------------------------------------------------------------------------
__global__ void __launch_bounds__(128) k_out(const float* __restrict__ wl,
                                             const float* __restrict__ bo,
                                             float* __restrict__ out)
{
    __shared__ float sh[256];
    const int b = blockIdx.x, o = threadIdx.x;
    sh[o]       = g_hfin[(size_t)b * H_ + o];
    sh[o + 128] = g_hfin[(size_t)b * H_ + o + 128];
    __syncthreads();

    float acc = bo[o];
    const float4* wp = (const float4*)(wl + (size_t)o * H_);
#pragma unroll 8
    for (int q = 0; q < 64; q++) {
        const float4 w = wp[q];
        const float4 h = *(const float4*)(sh + q * 4);
        acc += w.x * h.x + w.y * h.y + w.z * h.z + w.w * h.w;
    }
    out[(size_t)b * OUT_ + o] = acc;
}

// ---------------------------------------------------------------------------
extern "C" void kernel_launch(void* const* d_in, const int* in_sizes, int n_in,
                              void* d_out, int out_size)
{
    (void)in_sizes; (void)n_in; (void)out_size;
    const float* x   = (const float*)d_in[0];  // (B,T,IN)
    const float* wih = (const float*)d_in[1];  // (3H,IN)
    const float* whh = (const float*)d_in[2];  // (3H,H)
    const float* bg  = (const float*)d_in[3];  // (3H)
    const float* bnn = (const float*)d_in[4];  // (H)
    const float* wl  = (const float*)d_in[5];  // (OUT,H)
    const float* bo  = (const float*)d_in[6];  // (OUT)
    float* out = (float*)d_out;                // (B,OUT)

    cudaFuncSetAttribute(k_ih,  cudaFuncAttributeMaxDynamicSharedMemorySize, P1_SMEM_BYTES);
    cudaFuncSetAttribute(k_rec, cudaFuncAttributeMaxDynamicSharedMemorySize, REC_SMEM_BYTES);

    k_ih<<<dim3((B_ * T_) / 128, G3_ / 128), 256, P1_SMEM_BYTES>>>(x, wih, bg);
    k_rec<<<128, 128, REC_SMEM_BYTES>>>(whh, bnn);
    k_out<<<B_, 128>>>(wl, bo, out);
}

// round 7
// speedup vs baseline: 1.5927x; 1.5927x over previous
#include <cuda_runtime.h>
#include <cstdint>
#include <math.h>

// Problem dims
#define B_   512
#define T_   512
#define IN_  128
#define H_   256
#define G3_  768   // 3*H
#define OUT_ 128

__device__ float g_ig[(size_t)B_ * T_ * G3_];     // ~805 MB  [B][T][3H]
__device__ float g_hfin[(size_t)B_ * H_];

typedef unsigned long long ull;

// ---------------- packed fp32 helpers (Blackwell f32x2) --------------------
__device__ __forceinline__ ull pk2(float lo, float hi) {
    ull r;
    asm("mov.b64 %0, {%1, %2};" : "=l"(r) : "f"(lo), "f"(hi));
    return r;
}
__device__ __forceinline__ void fma2(ull& d, ull a, ull b) {
    asm("fma.rn.f32x2 %0, %1, %2, %0;" : "+l"(d) : "l"(a), "l"(b));
}
__device__ __forceinline__ void add2(ull& d, ull a) {
    asm("add.rn.f32x2 %0, %0, %1;" : "+l"(d) : "l"(a));
}
__device__ __forceinline__ float2 upk(ull v) {
    float2 f;
    asm("mov.b64 {%0, %1}, %2;" : "=f"(f.x), "=f"(f.y) : "l"(v));
    return f;
}

// ---------------------------------------------------------------------------
// Phase 1: ig = X @ W_ih^T + bias   (M=262144, N=768, K=128)
// 128x128 tile, kc=64 two-chunk, 8x8 outputs/thread, f32x2 FMAs.
// 66KB smem -> 2 CTAs/SM (4 warps/SMSP). bn = blockIdx.x so consecutive CTAs
// share the X tile in L2.
// ---------------------------------------------------------------------------
#define SA_STR 132
#define P1_KC  64
#define P1_SMEM_FLOATS (P1_KC * SA_STR + P1_KC * 128)   // 16640
#define P1_SMEM_BYTES  (P1_SMEM_FLOATS * 4)             // 66560

__global__ void __launch_bounds__(256, 2) k_ih(const float* __restrict__ X,
                                               const float* __restrict__ W,
                                               const float* __restrict__ bias)
{
    extern __shared__ float sm1[];
    float* sA = sm1;                  // [k(64)][m(128)] stride SA_STR
    float* sB = sm1 + P1_KC * SA_STR; // [k(64)][n(128)]

    const int tid = threadIdx.x;
    const int bn = blockIdx.x;        // 0..5
    const int bm = blockIdx.y;        // 0..2047
    const int ty = tid >> 4, tx = tid & 15;

    ull acc[4][8];
#pragma unroll
    for (int i = 0; i < 4; i++)
#pragma unroll
        for (int j = 0; j < 8; j++) acc[i][j] = 0ULL;

    for (int kk = 0; kk < 128; kk += P1_KC) {
        if (kk) __syncthreads();
        // stage A (transpose): 128 rows x 64 k
        {
            const int row = tid >> 1;
            const int khf = (tid & 1) * 32;
            const float* xs = X + ((size_t)(bm * 128 + row)) * 128 + kk + khf;
            const float* ws = W + ((size_t)(bn * 128 + row)) * 128 + kk + khf;
#pragma unroll
            for (int q = 0; q < 8; q++) {
                const float4 xv = *(const float4*)(xs + q * 4);
                const float4 wv = *(const float4*)(ws + q * 4);
                const int k0 = khf + q * 4;
                sA[(k0 + 0) * SA_STR + row] = xv.x;
                sA[(k0 + 1) * SA_STR + row] = xv.y;
                sA[(k0 + 2) * SA_STR + row] = xv.z;
                sA[(k0 + 3) * SA_STR + row] = xv.w;
                sB[(k0 + 0) * 128 + row] = wv.x;
                sB[(k0 + 1) * 128 + row] = wv.y;
                sB[(k0 + 2) * 128 + row] = wv.z;
                sB[(k0 + 3) * 128 + row] = wv.w;
            }
        }
        __syncthreads();

        const float* aBase = sA + ty * 8;
        const float* bBase = sB + tx * 8;

#pragma unroll 8
        for (int k = 0; k < P1_KC; k++) {
            const ulonglong2 aL = *(const ulonglong2*)(aBase + k * SA_STR);
            const ulonglong2 aH = *(const ulonglong2*)(aBase + k * SA_STR + 4);
            const float4 bv0 = *(const float4*)(bBase + k * 128);
            const float4 bv1 = *(const float4*)(bBase + k * 128 + 4);
            const ull ap[4] = {aL.x, aL.y, aH.x, aH.y};
            ull bd[8];
            bd[0] = pk2(bv0.x, bv0.x); bd[1] = pk2(bv0.y, bv0.y);
            bd[2] = pk2(bv0.z, bv0.z); bd[3] = pk2(bv0.w, bv0.w);
            bd[4] = pk2(bv1.x, bv1.x); bd[5] = pk2(bv1.y, bv1.y);
            bd[6] = pk2(bv1.z, bv1.z); bd[7] = pk2(bv1.w, bv1.w);
#pragma unroll
            for (int i = 0; i < 4; i++)
#pragma unroll
                for (int j = 0; j < 8; j++)
                    fma2(acc[i][j], ap[i], bd[j]);
        }
    }

    // epilogue: acc[i][j] = rows (ty*8+2i, +1), col bn*128 + tx*8 + j
    const float4 bb0 = *(const float4*)(bias + bn * 128 + tx * 8);
    const float4 bb1 = *(const float4*)(bias + bn * 128 + tx * 8 + 4);
#pragma unroll
    for (int i = 0; i < 4; i++) {
        float2 c[8];
#pragma unroll
        for (int j = 0; j < 8; j++) c[j] = upk(acc[i][j]);
        float* r0 = g_ig + ((size_t)(bm * 128 + ty * 8 + 2 * i)) * G3_ + bn * 128 + tx * 8;
        float* r1 = r0 + G3_;
        *(float4*)(r0)     = make_float4(c[0].x + bb0.x, c[1].x + bb0.y, c[2].x + bb0.z, c[3].x + bb0.w);
        *(float4*)(r0 + 4) = make_float4(c[4].x + bb1.x, c[5].x + bb1.y, c[6].x + bb1.z, c[7].x + bb1.w);
        *(float4*)(r1)     = make_float4(c[0].y + bb0.x, c[1].y + bb0.y, c[2].y + bb0.z, c[3].y + bb0.w);
        *(float4*)(r1 + 4) = make_float4(c[4].y + bb1.x, c[5].y + bb1.y, c[6].y + bb1.z, c[7].y + bb1.w);
    }
}

// ---------------------------------------------------------------------------
// Phase 2: GRU recurrence. Cluster of 4 CTAs; rank c owns 64 hidden units
// (W_hh chunk resident, 192KB). 256 threads = 64 units x 2 rowgroups x
// 2 k-halves: each thread does 128 k-iters for 8 rows; halves combined via a
// 12KB smem slab. Single h buffer + 2 cluster syncs/step. Paired-k h loads
// (LDS.128 covers 2 k) keep smem under the fma2 floor.
// ---------------------------------------------------------------------------
__device__ __forceinline__ uint32_t smem_u32(const void* p) {
    uint32_t a;
    asm("{ .reg .u64 t; cvta.to.shared.u64 t, %1; cvt.u32.u64 %0, t; }" : "=r"(a) : "l"(p));
    return a;
}
__device__ __forceinline__ uint32_t mapa_u32(uint32_t a, uint32_t rank) {
    uint32_t r;
    asm("mapa.shared::cluster.u32 %0, %1, %2;" : "=r"(r) : "r"(a), "r"(rank));
    return r;
}
__device__ __forceinline__ void stc_b64(uint32_t a, ull v) {
    asm volatile("st.shared::cluster.b64 [%0], %1;" :: "r"(a), "l"(v) : "memory");
}
__device__ __forceinline__ void cluster_sync_() {
    asm volatile("barrier.cluster.arrive.aligned;" ::: "memory");
    asm volatile("barrier.cluster.wait.aligned;"   ::: "memory");
}
// sigmoid / tanh via MUFU ex2 path: tanh(x) = 2*sigmoid(2x) - 1
__device__ __forceinline__ float gru_cell(float igr, float igz, float ign,
                                          float ar, float az, float an,
                                          float bnv, float hp) {
    const float r = __fdividef(1.f, 1.f + __expf(-(igr + ar)));
    const float z = __fdividef(1.f, 1.f + __expf(-(igz + az)));
    const float a = ign + r * (an + bnv);
    const float n = __fdividef(2.f, 1.f + __expf(-2.f * a)) - 1.f;
    return n + z * (hp - n);
}

// smem: sW 49152 f + sH 4096 f + sRed 1536 ull (12288 B) = 225280 B
#define SW_FLOATS  (3 * 256 * 64)
#define SH_FLOATS  (8 * 256 * 2)
#define REC_SMEM_BYTES ((SW_FLOATS + SH_FLOATS) * 4 + 128 * 12 * 8)

__global__ void __launch_bounds__(256, 1) __cluster_dims__(4, 1, 1)
k_rec(const float* __restrict__ Whh, const float* __restrict__ bn)
{
    extern __shared__ float sm[];
    float*  sW   = sm;                          // [gate][k][unit] : 3*256*64
    float2* sH   = (float2*)(sm + SW_FLOATS);   // [rowpair(8)][unit-as-k(256)]
    ull*    sRed = (ull*)(sm + SW_FLOATS + SH_FLOATS);  // [128][12]

    const int tid = threadIdx.x;
    const int c   = blockIdx.x & 3;   // cluster rank (unit chunk)
    const int cl  = blockIdx.x >> 2;  // cluster id: batch rows [cl*16, +16)

    // Stage W_hh chunk, transposed to unit-contiguous layout
    for (int flat = tid; flat < 3 * 64 * 64; flat += 256) {
        const int kv  = flat / 192;
        const int rem = flat - kv * 192;
        const int g   = rem >> 6;
        const int uu  = rem & 63;
        const float4 v = *(const float4*)(Whh + ((size_t)(g * 256 + c * 64 + uu)) * 256 + kv * 4);
        float* d = sW + (g * 256 + kv * 4) * 64 + uu;
        d[0] = v.x; d[64] = v.y; d[128] = v.z; d[192] = v.w;
    }
    for (int i = tid; i < 2048; i += 256) sH[i] = make_float2(0.f, 0.f);  // h_0 = 0
    __syncthreads();
    cluster_sync_();

    const int u   = tid & 63;           // unit within chunk
    const int rg  = (tid >> 6) & 1;     // rowgroup (8 rows each)
    const int kh  = tid >> 7;           // k-half
    const int gu  = c * 64 + u;
    const int rp0 = rg * 4;             // rowpairs rp0..rp0+3
    const int b0  = cl * 16 + rg * 8;
    const int kbase = kh * 128;

    const float bnv = bn[gu];

    const uint32_t ah = smem_u32(sH);
    uint32_t pp[4];
#pragma unroll
    for (int r = 0; r < 4; r++) pp[r] = mapa_u32(ah, r);

    const float* wr = sW + u;
    const float* wz = sW + 256 * 64 + u;
    const float* wn = sW + 512 * 64 + u;

    const size_t rstr = (size_t)T_ * G3_;
    const float* igb = g_ig + (size_t)b0 * rstr + gu;

    uint32_t off[4];
#pragma unroll
    for (int x = 0; x < 4; x++) off[x] = (uint32_t)(((rp0 + x) * 256 + gu) * 8);

    const ull* hsrc = (const ull*)sH;
    const ulonglong2* h0p = (const ulonglong2*)(hsrc + (rp0 + 0) * 256 + kbase);
    const ulonglong2* h1p = (const ulonglong2*)(hsrc + (rp0 + 1) * 256 + kbase);
    const ulonglong2* h2p = (const ulonglong2*)(hsrc + (rp0 + 2) * 256 + kbase);
    const ulonglong2* h3p = (const ulonglong2*)(hsrc + (rp0 + 3) * 256 + kbase);

    for (int t = 0; t < T_; t++) {
        // prefetch input gates (kh==0 warps only; consumed after the k-loop)
        float igr[8], igz[8], ign[8];
        if (kh == 0) {
            const size_t tb = (size_t)t * G3_;
#pragma unroll
            for (int j = 0; j < 8; j++) {
                const float* p = igb + (size_t)j * rstr + tb;
                igr[j] = p[0]; igz[j] = p[256]; ign[j] = p[512];
            }
        }

        ull aR[4] = {0,0,0,0}, aZ[4] = {0,0,0,0}, aN[4] = {0,0,0,0};

#pragma unroll 8
        for (int i = 0; i < 64; i++) {
            const int k0 = (kbase + 2 * i) * 64;
            const float w0a = wr[k0], w0b = wr[k0 + 64];
            const float w1a = wz[k0], w1b = wz[k0 + 64];
            const float w2a = wn[k0], w2b = wn[k0 + 64];
            const ulonglong2 h0 = h0p[i];
            const ulonglong2 h1 = h1p[i];
            const ulonglong2 h2 = h2p[i];
            const ulonglong2 h3 = h3p[i];
            const ull w0A = pk2(w0a, w0a), w0B = pk2(w0b, w0b);
            const ull w1A = pk2(w1a, w1a), w1B = pk2(w1b, w1b);
            const ull w2A = pk2(w2a, w2a), w2B = pk2(w2b, w2b);
            fma2(aR[0], w0A, h0.x); fma2(aR[1], w0A, h1.x); fma2(aR[2], w0A, h2.x); fma2(aR[3], w0A, h3.x);
            fma2(aZ[0], w1A, h0.x); fma2(aZ[1], w1A, h1.x); fma2(aZ[2], w1A, h2.x); fma2(aZ[3], w1A, h3.x);
            fma2(aN[0], w2A, h0.x); fma2(aN[1], w2A, h1.x); fma2(aN[2], w2A, h2.x); fma2(aN[3], w2A, h3.x);
            fma2(aR[0], w0B, h0.y); fma2(aR[1], w0B, h1.y); fma2(aR[2], w0B, h2.y); fma2(aR[3], w0B, h3.y);
            fma2(aZ[0], w1B, h0.y); fma2(aZ[1], w1B, h1.y); fma2(aZ[2], w1B, h2.y); fma2(aZ[3], w1B, h3.y);
            fma2(aN[0], w2B, h0.y); fma2(aN[1], w2B, h1.y); fma2(aN[2], w2B, h2.y); fma2(aN[3], w2B, h3.y);
        }

        float2 hp[4];
        if (kh == 1) {
            // publish partials for the kh==0 partner thread (tid-128)
            ulonglong2* red = (ulonglong2*)(sRed + (size_t)(tid - 128) * 12);
            red[0] = make_ulonglong2(aR[0], aR[1]);
            red[1] = make_ulonglong2(aR[2], aR[3]);
            red[2] = make_ulonglong2(aZ[0], aZ[1]);
            red[3] = make_ulonglong2(aZ[2], aZ[3]);
            red[4] = make_ulonglong2(aN[0], aN[1]);
            red[5] = make_ulonglong2(aN[2], aN[3]);
        } else {
            // previous h for own unit (must read before peers overwrite)
#pragma unroll
            for (int x = 0; x < 4; x++) hp[x] = sH[(rp0 + x) * 256 + gu];
        }

        cluster_sync_();  // sRed visible; all cluster reads of sH complete

        if (kh == 0) {
            const ulonglong2* red = (const ulonglong2*)(sRed + (size_t)tid * 12);
            const ulonglong2 r0 = red[0], r1 = red[1], r2 = red[2];
            const ulonglong2 r3 = red[3], r4 = red[4], r5 = red[5];
            add2(aR[0], r0.x); add2(aR[1], r0.y); add2(aR[2], r1.x); add2(aR[3], r1.y);
            add2(aZ[0], r2.x); add2(aZ[1], r2.y); add2(aZ[2], r3.x); add2(aZ[3], r3.y);
            add2(aN[0], r4.x); add2(aN[1], r4.y); add2(aN[2], r5.x); add2(aN[3], r5.y);

#pragma unroll
            for (int x = 0; x < 4; x++) {
                const float2 ar = upk(aR[x]);
                const float2 az = upk(aZ[x]);
                const float2 an = upk(aN[x]);
                const float hx = gru_cell(igr[2*x],   igz[2*x],   ign[2*x],   ar.x, az.x, an.x, bnv, hp[x].x);
                const float hy = gru_cell(igr[2*x+1], igz[2*x+1], ign[2*x+1], ar.y, az.y, an.y, bnv, hp[x].y);
                const ull hn = pk2(hx, hy);
#pragma unroll
                for (int r = 0; r < 4; r++) stc_b64(pp[r] + off[x], hn);
            }
        }
        cluster_sync_();  // h_{t+1} visible everywhere
    }

    // final h -> g_hfin
    for (int i = tid; i < 8 * 64; i += 256) {
        const int rp = i >> 6, uu = i & 63;
        const float2 v = sH[rp * 256 + c * 64 + uu];
        float* d = g_hfin + (size_t)(cl * 16 + rp * 2) * H_ + c * 64 + uu;
        d[0]  = v.x;
        d[H_] = v.y;
    }
}

// ---------------------------------------------------------------------------
// Phase 3: out = h_final @ w_lin^T + bias_out   (512 x 128, trivial)
// ---------------------------------------------------------------------------
__global__ void __launch_bounds__(128) k_out(const float* __restrict__ wl,
                                             const float* __restrict__ bo,
                                             float* __restrict__ out)
{
    __shared__ float sh[256];
    const int b = blockIdx.x, o = threadIdx.x;
    sh[o]       = g_hfin[(size_t)b * H_ + o];
    sh[o + 128] = g_hfin[(size_t)b * H_ + o + 128];
    __syncthreads();

    float acc = bo[o];
    const float4* wp = (const float4*)(wl + (size_t)o * H_);
#pragma unroll 8
    for (int q = 0; q < 64; q++) {
        const float4 w = wp[q];
        const float4 h = *(const float4*)(sh + q * 4);
        acc += w.x * h.x + w.y * h.y + w.z * h.z + w.w * h.w;
    }
    out[(size_t)b * OUT_ + o] = acc;
}

// ---------------------------------------------------------------------------
extern "C" void kernel_launch(void* const* d_in, const int* in_sizes, int n_in,
                              void* d_out, int out_size)
{
    (void)in_sizes; (void)n_in; (void)out_size;
    const float* x   = (const float*)d_in[0];  // (B,T,IN)
    const float* wih = (const float*)d_in[1];  // (3H,IN)
    const float* whh = (const float*)d_in[2];  // (3H,H)
    const float* bg  = (const float*)d_in[3];  // (3H)
    const float* bnn = (const float*)d_in[4];  // (H)
    const float* wl  = (const float*)d_in[5];  // (OUT,H)
    const float* bo  = (const float*)d_in[6];  // (OUT)
    float* out = (float*)d_out;                // (B,OUT)

    cudaFuncSetAttribute(k_ih,  cudaFuncAttributeMaxDynamicSharedMemorySize, P1_SMEM_BYTES);
    cudaFuncSetAttribute(k_rec, cudaFuncAttributeMaxDynamicSharedMemorySize, REC_SMEM_BYTES);

    k_ih<<<dim3(G3_ / 128, (B_ * T_) / 128), 256, P1_SMEM_BYTES>>>(x, wih, bg);
    k_rec<<<128, 256, REC_SMEM_BYTES>>>(whh, bnn);
    k_out<<<B_, 128>>>(wl, bo, out);
}

// round 9
// speedup vs baseline: 1.7859x; 1.1213x over previous
#include <cuda_runtime.h>
#include <cuda_bf16.h>
#include <cstdint>
#include <math.h>

// Problem dims
#define B_   512
#define T_   512
#define IN_  128
#define H_   256
#define G3_  768   // 3*H
#define OUT_ 128

__device__ float g_ig[(size_t)B_ * T_ * G3_];     // ~805 MB  [B][T][3H]
__device__ float g_hfin[(size_t)B_ * H_];

typedef unsigned long long ull;

// ---------------- packed fp32 helpers (Blackwell f32x2) --------------------
__device__ __forceinline__ ull pk2(float lo, float hi) {
    ull r;
    asm("mov.b64 %0, {%1, %2};" : "=l"(r) : "f"(lo), "f"(hi));
    return r;
}
__device__ __forceinline__ void fma2(ull& d, ull a, ull b) {
    asm("fma.rn.f32x2 %0, %1, %2, %0;" : "+l"(d) : "l"(a), "l"(b));
}
__device__ __forceinline__ void add2(ull& d, ull a) {
    asm("add.rn.f32x2 %0, %0, %1;" : "+l"(d) : "l"(a));
}
__device__ __forceinline__ float2 upk(ull v) {
    float2 f;
    asm("mov.b64 {%0, %1}, %2;" : "=f"(f.x), "=f"(f.y) : "l"(v));
    return f;
}

// ---------------- generic smem / cluster helpers ---------------------------
__device__ __forceinline__ uint32_t smem_u32(const void* p) {
    uint32_t a;
    asm("{ .reg .u64 t; cvta.to.shared.u64 t, %1; cvt.u32.u64 %0, t; }" : "=r"(a) : "l"(p));
    return a;
}
__device__ __forceinline__ uint32_t mapa_u32(uint32_t a, uint32_t rank) {
    uint32_t r;
    asm("mapa.shared::cluster.u32 %0, %1, %2;" : "=r"(r) : "r"(a), "r"(rank));
    return r;
}
__device__ __forceinline__ void stc_b64(uint32_t a, ull v) {
    asm volatile("st.shared::cluster.b64 [%0], %1;" :: "r"(a), "l"(v) : "memory");
}
__device__ __forceinline__ void cluster_sync_() {
    asm volatile("barrier.cluster.arrive.aligned;" ::: "memory");
    asm volatile("barrier.cluster.wait.aligned;"   ::: "memory");
}

// ---------------- mma.sync helpers (sm_80-era HMMA, valid on sm_100) -------
__device__ __forceinline__ void ldsm_x4(uint32_t* r, uint32_t addr) {
    asm volatile("ldmatrix.sync.aligned.m8n8.x4.shared.b16 {%0,%1,%2,%3}, [%4];"
                 : "=r"(r[0]), "=r"(r[1]), "=r"(r[2]), "=r"(r[3]) : "r"(addr));
}
__device__ __forceinline__ void ldsm_x2(uint32_t* r, uint32_t addr) {
    asm volatile("ldmatrix.sync.aligned.m8n8.x2.shared.b16 {%0,%1}, [%2];"
                 : "=r"(r[0]), "=r"(r[1]) : "r"(addr));
}
__device__ __forceinline__ void mma_bf16(float* d, const uint32_t* a, const uint32_t* b) {
    asm volatile(
        "mma.sync.aligned.m16n8k16.row.col.f32.bf16.bf16.f32 "
        "{%0,%1,%2,%3}, {%4,%5,%6,%7}, {%8,%9}, {%0,%1,%2,%3};"
        : "+f"(d[0]), "+f"(d[1]), "+f"(d[2]), "+f"(d[3])
        : "r"(a[0]), "r"(a[1]), "r"(a[2]), "r"(a[3]), "r"(b[0]), "r"(b[1]));
}

// ---------------------------------------------------------------------------
// Phase 1 (HMMA): ig = X @ W_ih^T + bias via bf16-split mma.sync.
// 128x128 tile, K=128. X,W split hi/lo bf16; D = XhiWhi + XhiWlo + XloWhi
// (fp32 accum). 8 warps = 2 m-groups x 4 n-groups; each warp 64x32.
// smem: 4 tiles of 128 x (stride 136) bf16 = 139264 B -> 1 CTA/SM.
// ---------------------------------------------------------------------------
#define P1_STR   136                       // bf16 elements per row (128 + 8 pad)
#define P1_TILE  (128 * P1_STR * 2)        // 34816 B per matrix
#define P1_SMEM_BYTES (4 * P1_TILE)        // 139264 B

__global__ void __launch_bounds__(256, 1)
k_ih_mma(const float* __restrict__ X, const float* __restrict__ W,
         const float* __restrict__ bias)
{
    extern __shared__ __nv_bfloat16 smb[];
    __nv_bfloat16* sAhi = smb;
    __nv_bfloat16* sAlo = smb + 128 * P1_STR;
    __nv_bfloat16* sBhi = smb + 2 * 128 * P1_STR;
    __nv_bfloat16* sBlo = smb + 3 * 128 * P1_STR;

    const int tid  = threadIdx.x;
    const int wid  = tid >> 5, lane = tid & 31;
    const int bn   = blockIdx.x;      // 0..5
    const int bm   = blockIdx.y;      // 0..2047

    // ---- stage + hi/lo split: thread = (row, k-half) ----
    {
        const int row = tid >> 1;
        const int kh  = (tid & 1) * 64;
        const float* xs = X + ((size_t)(bm * 128 + row)) * 128 + kh;
        const float* ws = W + ((size_t)(bn * 128 + row)) * 128 + kh;
        __nv_bfloat16* ah = sAhi + row * P1_STR + kh;
        __nv_bfloat16* al = sAlo + row * P1_STR + kh;
        __nv_bfloat16* bh = sBhi + row * P1_STR + kh;
        __nv_bfloat16* bl = sBlo + row * P1_STR + kh;
#pragma unroll
        for (int q = 0; q < 16; q++) {
            const float4 xv = *(const float4*)(xs + q * 4);
            const float4 wv = *(const float4*)(ws + q * 4);
            __nv_bfloat162 xh0 = __floats2bfloat162_rn(xv.x, xv.y);
            __nv_bfloat162 xh1 = __floats2bfloat162_rn(xv.z, xv.w);
            __nv_bfloat162 wh0 = __floats2bfloat162_rn(wv.x, wv.y);
            __nv_bfloat162 wh1 = __floats2bfloat162_rn(wv.z, wv.w);
            __nv_bfloat162 xl0 = __floats2bfloat162_rn(xv.x - __bfloat162float(xh0.x),
                                                       xv.y - __bfloat162float(xh0.y));
            __nv_bfloat162 xl1 = __floats2bfloat162_rn(xv.z - __bfloat162float(xh1.x),
                                                       xv.w - __bfloat162float(xh1.y));
            __nv_bfloat162 wl0 = __floats2bfloat162_rn(wv.x - __bfloat162float(wh0.x),
                                                       wv.y - __bfloat162float(wh0.y));
            __nv_bfloat162 wl1 = __floats2bfloat162_rn(wv.z - __bfloat162float(wh1.x),
                                                       wv.w - __bfloat162float(wh1.y));
            *(__nv_bfloat162*)(ah + q * 4)     = xh0;
            *(__nv_bfloat162*)(ah + q * 4 + 2) = xh1;
            *(__nv_bfloat162*)(al + q * 4)     = xl0;
            *(__nv_bfloat162*)(al + q * 4 + 2) = xl1;
            *(__nv_bfloat162*)(bh + q * 4)     = wh0;
            *(__nv_bfloat162*)(bh + q * 4 + 2) = wh1;
            *(__nv_bfloat162*)(bl + q * 4)     = wl0;
            *(__nv_bfloat162*)(bl + q * 4 + 2) = wl1;
        }
    }
    __syncthreads();

    // ---- warp tiling: wm in {0,1} (64 rows), wn in {0..3} (32 cols) ----
    const int wm = wid & 1;
    const int wn = wid >> 1;

    // ldmatrix lane addressing (byte offsets within a tile)
    const int rowA = wm * 64 + (lane & 15);          // + mt*16
    const int kA   = (lane >> 4) * 8;                // + ks*16
    const int rowB = wn * 32 + (lane & 7);           // + nt*8
    const int kB   = ((lane >> 3) & 1) * 8;          // + ks*16

    const uint32_t sb   = smem_u32(smb);
    const uint32_t aHi0 = sb + (uint32_t)(2 * (rowA * P1_STR + kA));
    const uint32_t aLo0 = aHi0 + P1_TILE;
    const uint32_t bHi0 = sb + 2u * P1_TILE + (uint32_t)(2 * (rowB * P1_STR + kB));
    const uint32_t bLo0 = bHi0 + P1_TILE;

    float acc[4][4][4];
#pragma unroll
    for (int mt = 0; mt < 4; mt++)
#pragma unroll
        for (int nt = 0; nt < 4; nt++)
#pragma unroll
            for (int e = 0; e < 4; e++) acc[mt][nt][e] = 0.f;

#pragma unroll
    for (int ks = 0; ks < 8; ks++) {
        const uint32_t kso = (uint32_t)(2 * (ks * 16));
        uint32_t bh[4][2], bl[4][2];
#pragma unroll
        for (int nt = 0; nt < 4; nt++) {
            const uint32_t bo = (uint32_t)(2 * (nt * 8 * P1_STR)) + kso;
            ldsm_x2(bh[nt], bHi0 + bo);
            ldsm_x2(bl[nt], bLo0 + bo);
        }
#pragma unroll
        for (int mt = 0; mt < 4; mt++) {
            const uint32_t ao = (uint32_t)(2 * (mt * 16 * P1_STR)) + kso;
            uint32_t ah[4], al[4];
            ldsm_x4(ah, aHi0 + ao);
            ldsm_x4(al, aLo0 + ao);
#pragma unroll
            for (int nt = 0; nt < 4; nt++) {
                mma_bf16(acc[mt][nt], ah, bh[nt]);   // hi*hi
                mma_bf16(acc[mt][nt], ah, bl[nt]);   // hi*lo
                mma_bf16(acc[mt][nt], al, bh[nt]);   // lo*hi
            }
        }
    }

    // ---- epilogue: C rows = groupID/+8, cols = 2*(lane&3) ----
    const int grp = lane >> 2;
    const int qc  = (lane & 3) * 2;
#pragma unroll
    for (int mt = 0; mt < 4; mt++) {
        const int r0 = bm * 128 + wm * 64 + mt * 16 + grp;
#pragma unroll
        for (int nt = 0; nt < 4; nt++) {
            const int col = bn * 128 + wn * 32 + nt * 8 + qc;
            const float2 bb = *(const float2*)(bias + col);
            float* d0 = g_ig + (size_t)r0 * G3_ + col;
            float* d1 = d0 + (size_t)8 * G3_;
            *(float2*)d0 = make_float2(acc[mt][nt][0] + bb.x, acc[mt][nt][1] + bb.y);
            *(float2*)d1 = make_float2(acc[mt][nt][2] + bb.x, acc[mt][nt][3] + bb.y);
        }
    }
}

// ---------------------------------------------------------------------------
// Phase 2: GRU recurrence (unchanged from R7 passing version).
// ---------------------------------------------------------------------------
__device__ __forceinline__ float gru_cell(float igr, float igz, float ign,
                                          float ar, float az, float an,
                                          float bnv, float hp) {
    const float r = __fdividef(1.f, 1.f + __expf(-(igr + ar)));
    const float z = __fdividef(1.f, 1.f + __expf(-(igz + az)));
    const float a = ign + r * (an + bnv);
    const float n = __fdividef(2.f, 1.f + __expf(-2.f * a)) - 1.f;
    return n + z * (hp - n);
}

#define SW_FLOATS  (3 * 256 * 64)
#define SH_FLOATS  (8 * 256 * 2)
#define REC_SMEM_BYTES ((SW_FLOATS + SH_FLOATS) * 4 + 128 * 12 * 8)

__global__ void __launch_bounds__(256, 1) __cluster_dims__(4, 1, 1)
k_rec(const float* __restrict__ Whh, const float* __restrict__ bn)
{
    extern __shared__ float sm[];
    float*  sW   = sm;                          // [gate][k][unit] : 3*256*64
    float2* sH   = (float2*)(sm + SW_FLOATS);   // [rowpair(8)][unit(256)]
    ull*    sRed = (ull*)(sm + SW_FLOATS + SH_FLOATS);  // [128][12]

    const int tid = threadIdx.x;
    const int c   = blockIdx.x & 3;
    const int cl  = blockIdx.x >> 2;

    for (int flat = tid; flat < 3 * 64 * 64; flat += 256) {
        const int kv  = flat / 192;
        const int rem = flat - kv * 192;
        const int g   = rem >> 6;
        const int uu  = rem & 63;
        const float4 v = *(const float4*)(Whh + ((size_t)(g * 256 + c * 64 + uu)) * 256 + kv * 4);
        float* d = sW + (g * 256 + kv * 4) * 64 + uu;
        d[0] = v.x; d[64] = v.y; d[128] = v.z; d[192] = v.w;
    }
    for (int i = tid; i < 2048; i += 256) sH[i] = make_float2(0.f, 0.f);
    __syncthreads();
    cluster_sync_();

    const int u   = tid & 63;
    const int rg  = (tid >> 6) & 1;
    const int kh  = tid >> 7;
    const int gu  = c * 64 + u;
    const int rp0 = rg * 4;
    const int b0  = cl * 16 + rg * 8;
    const int kbase = kh * 128;

    const float bnv = bn[gu];

    const uint32_t ah = smem_u32(sH);
    uint32_t pp[4];
#pragma unroll
    for (int r = 0; r < 4; r++) pp[r] = mapa_u32(ah, r);

    const float* wr = sW + u;
    const float* wz = sW + 256 * 64 + u;
    const float* wn = sW + 512 * 64 + u;

    const size_t rstr = (size_t)T_ * G3_;
    const float* igb = g_ig + (size_t)b0 * rstr + gu;

    uint32_t off[4];
#pragma unroll
    for (int x = 0; x < 4; x++) off[x] = (uint32_t)(((rp0 + x) * 256 + gu) * 8);

    const ull* hsrc = (const ull*)sH;
    const ulonglong2* h0p = (const ulonglong2*)(hsrc + (rp0 + 0) * 256 + kbase);
    const ulonglong2* h1p = (const ulonglong2*)(hsrc + (rp0 + 1) * 256 + kbase);
    const ulonglong2* h2p = (const ulonglong2*)(hsrc + (rp0 + 2) * 256 + kbase);
    const ulonglong2* h3p = (const ulonglong2*)(hsrc + (rp0 + 3) * 256 + kbase);

    for (int t = 0; t < T_; t++) {
        float igr[8], igz[8], ign[8];
        if (kh == 0) {
            const size_t tb = (size_t)t * G3_;
#pragma unroll
            for (int j = 0; j < 8; j++) {
                const float* p = igb + (size_t)j * rstr + tb;
                igr[j] = p[0]; igz[j] = p[256]; ign[j] = p[512];
            }
        }

        ull aR[4] = {0,0,0,0}, aZ[4] = {0,0,0,0}, aN[4] = {0,0,0,0};

#pragma unroll 8
        for (int i = 0; i < 64; i++) {
            const int k0 = (kbase + 2 * i) * 64;
            const float w0a = wr[k0], w0b = wr[k0 + 64];
            const float w1a = wz[k0], w1b = wz[k0 + 64];
            const float w2a = wn[k0], w2b = wn[k0 + 64];
            const ulonglong2 h0 = h0p[i];
            const ulonglong2 h1 = h1p[i];
            const ulonglong2 h2 = h2p[i];
            const ulonglong2 h3 = h3p[i];
            const ull w0A = pk2(w0a, w0a), w0B = pk2(w0b, w0b);
            const ull w1A = pk2(w1a, w1a), w1B = pk2(w1b, w1b);
            const ull w2A = pk2(w2a, w2a), w2B = pk2(w2b, w2b);
            fma2(aR[0], w0A, h0.x); fma2(aR[1], w0A, h1.x); fma2(aR[2], w0A, h2.x); fma2(aR[3], w0A, h3.x);
            fma2(aZ[0], w1A, h0.x); fma2(aZ[1], w1A, h1.x); fma2(aZ[2], w1A, h2.x); fma2(aZ[3], w1A, h3.x);
            fma2(aN[0], w2A, h0.x); fma2(aN[1], w2A, h1.x); fma2(aN[2], w2A, h2.x); fma2(aN[3], w2A, h3.x);
            fma2(aR[0], w0B, h0.y); fma2(aR[1], w0B, h1.y); fma2(aR[2], w0B, h2.y); fma2(aR[3], w0B, h3.y);
            fma2(aZ[0], w1B, h0.y); fma2(aZ[1], w1B, h1.y); fma2(aZ[2], w1B, h2.y); fma2(aZ[3], w1B, h3.y);
            fma2(aN[0], w2B, h0.y); fma2(aN[1], w2B, h1.y); fma2(aN[2], w2B, h2.y); fma2(aN[3], w2B, h3.y);
        }

        float2 hp[4];
        if (kh == 1) {
            ulonglong2* red = (ulonglong2*)(sRed + (size_t)(tid - 128) * 12);
            red[0] = make_ulonglong2(aR[0], aR[1]);
            red[1] = make_ulonglong2(aR[2], aR[3]);
            red[2] = make_ulonglong2(aZ[0], aZ[1]);
            red[3] = make_ulonglong2(aZ[2], aZ[3]);
            red[4] = make_ulonglong2(aN[0], aN[1]);
            red[5] = make_ulonglong2(aN[2], aN[3]);
        } else {
#pragma unroll
            for (int x = 0; x < 4; x++) hp[x] = sH[(rp0 + x) * 256 + gu];
        }

        cluster_sync_();

        if (kh == 0) {
            const ulonglong2* red = (const ulonglong2*)(sRed + (size_t)tid * 12);
            const ulonglong2 r0 = red[0], r1 = red[1], r2 = red[2];
            const ulonglong2 r3 = red[3], r4 = red[4], r5 = red[5];
            add2(aR[0], r0.x); add2(aR[1], r0.y); add2(aR[2], r1.x); add2(aR[3], r1.y);
            add2(aZ[0], r2.x); add2(aZ[1], r2.y); add2(aZ[2], r3.x); add2(aZ[3], r3.y);
            add2(aN[0], r4.x); add2(aN[1], r4.y); add2(aN[2], r5.x); add2(aN[3], r5.y);

#pragma unroll
            for (int x = 0; x < 4; x++) {
                const float2 ar = upk(aR[x]);
                const float2 az = upk(aZ[x]);
                const float2 an = upk(aN[x]);
                const float hx = gru_cell(igr[2*x],   igz[2*x],   ign[2*x],   ar.x, az.x, an.x, bnv, hp[x].x);
                const float hy = gru_cell(igr[2*x+1], igz[2*x+1], ign[2*x+1], ar.y, az.y, an.y, bnv, hp[x].y);
                const ull hn = pk2(hx, hy);
#pragma unroll
                for (int r = 0; r < 4; r++) stc_b64(pp[r] + off[x], hn);
            }
        }
        cluster_sync_();
    }

    for (int i = tid; i < 8 * 64; i += 256) {
        const int rp = i >> 6, uu = i & 63;
        const float2 v = sH[rp * 256 + c * 64 + uu];
        float* d = g_hfin + (size_t)(cl * 16 + rp * 2) * H_ + c * 64 + uu;
        d[0]  = v.x;
        d[H_] = v.y;
    }
}

// ---------------------------------------------------------------------------
// Phase 3: out = h_final @ w_lin^T + bias_out   (512 x 128, trivial)
// ---------------------------------------------------------------------------
__global__ void __launch_bounds__(128) k_out(const float* __restrict__ wl,
                                             const float* __restrict__ bo,
                                             float* __restrict__ out)
{
    __shared__ float sh[256];
    const int b = blockIdx.x, o = threadIdx.x;
    sh[o]       = g_hfin[(size_t)b * H_ + o];
    sh[o + 128] = g_hfin[(size_t)b * H_ + o + 128];
    __syncthreads();

    float acc = bo[o];
    const float4* wp = (const float4*)(wl + (size_t)o * H_);
#pragma unroll 8
    for (int q = 0; q < 64; q++) {
        const float4 w = wp[q];
        const float4 h = *(const float4*)(sh + q * 4);
        acc += w.x * h.x + w.y * h.y + w.z * h.z + w.w * h.w;
    }
    out[(size_t)b * OUT_ + o] = acc;
}

// ---------------------------------------------------------------------------
extern "C" void kernel_launch(void* const* d_in, const int* in_sizes, int n_in,
                              void* d_out, int out_size)
{
    (void)in_sizes; (void)n_in; (void)out_size;
    const float* x   = (const float*)d_in[0];  // (B,T,IN)
    const float* wih = (const float*)d_in[1];  // (3H,IN)
    const float* whh = (const float*)d_in[2];  // (3H,H)
    const float* bg  = (const float*)d_in[3];  // (3H)
    const float* bnn = (const float*)d_in[4];  // (H)
    const float* wl  = (const float*)d_in[5];  // (OUT,H)
    const float* bo  = (const float*)d_in[6];  // (OUT)
    float* out = (float*)d_out;                // (B,OUT)

    cudaFuncSetAttribute(k_ih_mma, cudaFuncAttributeMaxDynamicSharedMemorySize, P1_SMEM_BYTES);
    cudaFuncSetAttribute(k_rec,    cudaFuncAttributeMaxDynamicSharedMemorySize, REC_SMEM_BYTES);

    k_ih_mma<<<dim3(G3_ / 128, (B_ * T_) / 128), 256, P1_SMEM_BYTES>>>(x, wih, bg);
    k_rec<<<128, 256, REC_SMEM_BYTES>>>(whh, bnn);
    k_out<<<B_, 128>>>(wl, bo, out);
}

// round 10
// speedup vs baseline: 2.6797x; 1.5004x over previous
#include <cuda_runtime.h>
#include <cuda_bf16.h>
#include <cstdint>
#include <math.h>

// Problem dims
#define B_   512
#define T_   512
#define IN_  128
#define H_   256
#define G3_  768   // 3*H
#define OUT_ 128

__device__ float g_ig[(size_t)B_ * T_ * G3_];     // ~805 MB  [B][T][3H]
__device__ float g_hfin[(size_t)B_ * H_];

typedef unsigned long long ull;

// ---------------- generic smem / cluster helpers ---------------------------
__device__ __forceinline__ uint32_t smem_u32(const void* p) {
    uint32_t a;
    asm("{ .reg .u64 t; cvta.to.shared.u64 t, %1; cvt.u32.u64 %0, t; }" : "=r"(a) : "l"(p));
    return a;
}
__device__ __forceinline__ uint32_t mapa_u32(uint32_t a, uint32_t rank) {
    uint32_t r;
    asm("mapa.shared::cluster.u32 %0, %1, %2;" : "=r"(r) : "r"(a), "r"(rank));
    return r;
}
__device__ __forceinline__ void stc_b32(uint32_t a, uint32_t v) {
    asm volatile("st.shared::cluster.u32 [%0], %1;" :: "r"(a), "r"(v) : "memory");
}
__device__ __forceinline__ void cluster_sync_() {
    asm volatile("barrier.cluster.arrive.aligned;" ::: "memory");
    asm volatile("barrier.cluster.wait.aligned;"   ::: "memory");
}

// ---------------- mma.sync helpers (sm_80-era HMMA, valid on sm_100) -------
__device__ __forceinline__ void ldsm_x4(uint32_t* r, uint32_t addr) {
    asm volatile("ldmatrix.sync.aligned.m8n8.x4.shared.b16 {%0,%1,%2,%3}, [%4];"
                 : "=r"(r[0]), "=r"(r[1]), "=r"(r[2]), "=r"(r[3]) : "r"(addr));
}
__device__ __forceinline__ void ldsm_x2(uint32_t* r, uint32_t addr) {
    asm volatile("ldmatrix.sync.aligned.m8n8.x2.shared.b16 {%0,%1}, [%2];"
                 : "=r"(r[0]), "=r"(r[1]) : "r"(addr));
}
__device__ __forceinline__ void mma_bf16(float* d, const uint32_t* a, const uint32_t* b) {
    asm volatile(
        "mma.sync.aligned.m16n8k16.row.col.f32.bf16.bf16.f32 "
        "{%0,%1,%2,%3}, {%4,%5,%6,%7}, {%8,%9}, {%0,%1,%2,%3};"
        : "+f"(d[0]), "+f"(d[1]), "+f"(d[2]), "+f"(d[3])
        : "r"(a[0]), "r"(a[1]), "r"(a[2]), "r"(a[3]), "r"(b[0]), "r"(b[1]));
}

// bf16 hi/lo split of a float4 -> 4 packed bf16x2 (hi pair0, hi pair1, lo0, lo1)
__device__ __forceinline__ void split4(const float4 v,
                                       __nv_bfloat162& h0, __nv_bfloat162& h1,
                                       __nv_bfloat162& l0, __nv_bfloat162& l1) {
    h0 = __floats2bfloat162_rn(v.x, v.y);
    h1 = __floats2bfloat162_rn(v.z, v.w);
    l0 = __floats2bfloat162_rn(v.x - __bfloat162float(h0.x), v.y - __bfloat162float(h0.y));
    l1 = __floats2bfloat162_rn(v.z - __bfloat162float(h1.x), v.w - __bfloat162float(h1.y));
}

// ---------------------------------------------------------------------------
// Phase 1 (HMMA): ig = X @ W_ih^T + bias via bf16-split mma.sync.
// 128x64 tile, K=128 (2 chunks of 64). 8 warps = 2 m x 4 n; each warp 64x16.
// smem 55296 B + acc 32 regs -> 2 CTAs/SM. Chains reordered for dependency
// distance 8 between HMMAs on the same accumulator.
// ---------------------------------------------------------------------------
#define P1_STR  72                      // bf16/row (64 + 8 pad); gap 144B ≡ 4 mod 32 words
#define AHI_OFF 0
#define ALO_OFF (128 * P1_STR * 2)      // 18432
#define BHI_OFF (2 * 128 * P1_STR * 2)  // 36864
#define BLO_OFF (BHI_OFF + 64 * P1_STR * 2)  // 46080
#define P1_SMEM_BYTES (BLO_OFF + 64 * P1_STR * 2)  // 55296

__global__ void __launch_bounds__(256, 2)
k_ih_mma(const float* __restrict__ X, const float* __restrict__ W,
         const float* __restrict__ bias)
{
    extern __shared__ char smc[];
    const uint32_t sb = smem_u32(smc);
    const int tid  = threadIdx.x;
    const int wid  = tid >> 5, lane = tid & 31;
    const int bn   = blockIdx.x;      // 0..11 (64-col blocks)
    const int bm   = blockIdx.y;      // 0..2047

    const int wm = wid & 1;           // 64-row half
    const int wn = wid >> 1;          // 16-col quarter

    const uint32_t aHi0 = sb + AHI_OFF + 2u * ((wm * 64 + (lane & 15)) * P1_STR + (lane >> 4) * 8);
    const uint32_t aLo0 = aHi0 + (ALO_OFF - AHI_OFF);
    const uint32_t bHi0 = sb + BHI_OFF + 2u * ((wn * 16 + (lane & 7)) * P1_STR + ((lane >> 3) & 1) * 8);
    const uint32_t bLo0 = bHi0 + (BLO_OFF - BHI_OFF);

    float acc[4][2][4];
#pragma unroll
    for (int mt = 0; mt < 4; mt++)
#pragma unroll
        for (int nt = 0; nt < 2; nt++)
#pragma unroll
            for (int e = 0; e < 4; e++) acc[mt][nt][e] = 0.f;

    for (int kk = 0; kk < 128; kk += 64) {
        if (kk) __syncthreads();
        // stage A (128 rows x 64 k): thread = (row, k-half)
        {
            const int row = tid >> 1;
            const int kp  = (tid & 1) * 32;
            const float* xs = X + ((size_t)(bm * 128 + row)) * 128 + kk + kp;
            __nv_bfloat16* ah = (__nv_bfloat16*)(smc + AHI_OFF) + row * P1_STR + kp;
            __nv_bfloat16* al = (__nv_bfloat16*)(smc + ALO_OFF) + row * P1_STR + kp;
#pragma unroll
            for (int q = 0; q < 8; q++) {
                __nv_bfloat162 h0, h1, l0, l1;
                split4(*(const float4*)(xs + q * 4), h0, h1, l0, l1);
                *(__nv_bfloat162*)(ah + q * 4)     = h0;
                *(__nv_bfloat162*)(ah + q * 4 + 2) = h1;
                *(__nv_bfloat162*)(al + q * 4)     = l0;
                *(__nv_bfloat162*)(al + q * 4 + 2) = l1;
            }
        }
        // stage B (64 rows x 64 k): thread = (row, k-quarter)
        {
            const int row = tid >> 2;
            const int kp  = (tid & 3) * 16;
            const float* ws = W + ((size_t)(bn * 64 + row)) * 128 + kk + kp;
            __nv_bfloat16* bh = (__nv_bfloat16*)(smc + BHI_OFF) + row * P1_STR + kp;
            __nv_bfloat16* bl = (__nv_bfloat16*)(smc + BLO_OFF) + row * P1_STR + kp;
#pragma unroll
            for (int q = 0; q < 4; q++) {
                __nv_bfloat162 h0, h1, l0, l1;
                split4(*(const float4*)(ws + q * 4), h0, h1, l0, l1);
                *(__nv_bfloat162*)(bh + q * 4)     = h0;
                *(__nv_bfloat162*)(bh + q * 4 + 2) = h1;
                *(__nv_bfloat162*)(bl + q * 4)     = l0;
                *(__nv_bfloat162*)(bl + q * 4 + 2) = l1;
            }
        }
        __syncthreads();

#pragma unroll
        for (int ks = 0; ks < 4; ks++) {
            const uint32_t ko = (uint32_t)(ks * 32);
            uint32_t ah[4][4], al[4][4];
#pragma unroll
            for (int mt = 0; mt < 4; mt++) {
                ldsm_x4(ah[mt], aHi0 + (uint32_t)(mt * 16 * P1_STR * 2) + ko);
                ldsm_x4(al[mt], aLo0 + (uint32_t)(mt * 16 * P1_STR * 2) + ko);
            }
            uint32_t bh[2][2], bl[2][2];
#pragma unroll
            for (int nt = 0; nt < 2; nt++) {
                ldsm_x2(bh[nt], bHi0 + (uint32_t)(nt * 8 * P1_STR * 2) + ko);
                ldsm_x2(bl[nt], bLo0 + (uint32_t)(nt * 8 * P1_STR * 2) + ko);
            }
            // chain-major ordering: each acc revisited every 8 HMMAs
#pragma unroll
            for (int mt = 0; mt < 4; mt++)
#pragma unroll
                for (int nt = 0; nt < 2; nt++) mma_bf16(acc[mt][nt], ah[mt], bh[nt]);
#pragma unroll
            for (int mt = 0; mt < 4; mt++)
#pragma unroll
                for (int nt = 0; nt < 2; nt++) mma_bf16(acc[mt][nt], ah[mt], bl[nt]);
#pragma unroll
            for (int mt = 0; mt < 4; mt++)
#pragma unroll
                for (int nt = 0; nt < 2; nt++) mma_bf16(acc[mt][nt], al[mt], bh[nt]);
        }
    }

    // epilogue
    const int grp = lane >> 2;
    const int qc  = (lane & 3) * 2;
#pragma unroll
    for (int mt = 0; mt < 4; mt++) {
        const int r0 = bm * 128 + wm * 64 + mt * 16 + grp;
#pragma unroll
        for (int nt = 0; nt < 2; nt++) {
            const int col = bn * 64 + wn * 16 + nt * 8 + qc;
            const float2 bb = *(const float2*)(bias + col);
            float* d0 = g_ig + (size_t)r0 * G3_ + col;
            float* d1 = d0 + (size_t)8 * G3_;
            *(float2*)d0 = make_float2(acc[mt][nt][0] + bb.x, acc[mt][nt][1] + bb.y);
            *(float2*)d1 = make_float2(acc[mt][nt][2] + bb.x, acc[mt][nt][3] + bb.y);
        }
    }
}

// ---------------------------------------------------------------------------
// Phase 2 (HMMA): GRU recurrence. Cluster of 4 CTAs; rank c owns 192 gate
// rows (r,z,n for 64 units), W_hh chunk resident as bf16 hi/lo (198 KB).
// Per step: D[16 rows][192] = h @ W^T via m16n8k16 bf16-split (3 chains,
// fp32 accum); D staged in smem; GRU cells computed per-thread with hp kept
// in registers; new h written as bf16 hi/lo to all 4 CTAs via DSMEM.
// smem layout (bytes): Whi[0,101376) Wlo[101376,202752) hHi[202752,211200)
//                      hLo[211200,219648) D[219648,232448)  == 232448 total.
// ---------------------------------------------------------------------------
#define WSTR    264                 // bf16/row (256+8); gap 528B = 132w ≡ 4 mod 32
#define WLO_B   101376
#define HHI_B   202752
#define HLO_B   211200
#define D_B     219648
#define DSTR    200                 // floats
#define KR_SMEM_BYTES 232448

__device__ __forceinline__ float gru_cell(float igr, float igz, float ign,
                                          float ar, float az, float an,
                                          float bnv, float hp) {
    const float r = __fdividef(1.f, 1.f + __expf(-(igr + ar)));
    const float z = __fdividef(1.f, 1.f + __expf(-(igz + az)));
    const float a = ign + r * (an + bnv);
    const float n = __fdividef(2.f, 1.f + __expf(-2.f * a)) - 1.f;
    return n + z * (hp - n);
}

__global__ void __launch_bounds__(256, 1) __cluster_dims__(4, 1, 1)
k_rec_mma(const float* __restrict__ Whh, const float* __restrict__ bnb)
{
    extern __shared__ char smr[];
    const uint32_t sb = smem_u32(smr);
    const int tid = threadIdx.x;
    const int wid = tid >> 5, lane = tid & 31;
    const int c   = blockIdx.x & 3;   // cluster rank (unit chunk)
    const int cl  = blockIdx.x >> 2;  // cluster id: batch rows [cl*16, +16)

    // ---- stage W_hh chunk as bf16 hi/lo, local rows [r-units | z | n] ----
    if (tid < 192) {
        const int g = tid >> 6, u = tid & 63;
        const float* src = Whh + ((size_t)(g * 256 + c * 64 + u)) * 256;
        __nv_bfloat16* whi = (__nv_bfloat16*)(smr) + tid * WSTR;
        __nv_bfloat16* wlo = (__nv_bfloat16*)(smr + WLO_B) + tid * WSTR;
#pragma unroll 4
        for (int q = 0; q < 64; q++) {
            __nv_bfloat162 h0, h1, l0, l1;
            split4(*(const float4*)(src + q * 4), h0, h1, l0, l1);
            *(__nv_bfloat162*)(whi + q * 4)     = h0;
            *(__nv_bfloat162*)(whi + q * 4 + 2) = h1;
            *(__nv_bfloat162*)(wlo + q * 4)     = l0;
            *(__nv_bfloat162*)(wlo + q * 4 + 2) = l1;
        }
    }
    // zero h buffers (hi+lo, incl padding): 16896 B = 4224 words
    for (int i = tid; i < 4224; i += 256) ((uint32_t*)(smr + HHI_B))[i] = 0;
    __syncthreads();
    cluster_sync_();

    // ---- phase-A fragment addresses (warp wid owns n-tiles tn0..tn0+2) ----
    const int tn0 = wid * 3;
    const uint32_t aHi = sb + HHI_B + 2u * ((lane & 15) * WSTR + (lane >> 4) * 8);
    const uint32_t aLo = aHi + (HLO_B - HHI_B);
    uint32_t bAd[3];
#pragma unroll
    for (int nt = 0; nt < 3; nt++)
        bAd[nt] = sb + 2u * (((tn0 + nt) * 8 + (lane & 7)) * WSTR + ((lane >> 3) & 1) * 8);

    // ---- phase-B constants (warp == row-group: rows 2*wid, 2*wid+1) ------
    const int lu  = lane * 2;             // local units lu, lu+1
    const int gu  = c * 64 + lu;
    const int row0 = 2 * wid;
    const float2 bnv = *(const float2*)(bnb + gu);
    const float* ig0 = g_ig + ((size_t)(cl * 16 + row0)) * T_ * G3_ + gu;
    const float* ig1 = ig0 + (size_t)T_ * G3_;
    float* Dm = (float*)(smr + D_B);
    uint32_t pp[4];
#pragma unroll
    for (int r = 0; r < 4; r++) pp[r] = mapa_u32(sb, r);
    const uint32_t offH0 = HHI_B + 2u * (row0 * WSTR + gu);
    const uint32_t offH1 = HHI_B + 2u * ((row0 + 1) * WSTR + gu);
    float2 hp0 = make_float2(0.f, 0.f), hp1 = make_float2(0.f, 0.f);
    const int grp = lane >> 2, qc = (lane & 3) * 2;

    for (int t = 0; t < T_; t++) {
        // prefetch input gates for this thread's 2 rows x 2 units
        const float* p0 = ig0 + (size_t)t * G3_;
        const float* p1 = ig1 + (size_t)t * G3_;
        const float2 gr0 = *(const float2*)(p0);
        const float2 gz0 = *(const float2*)(p0 + 256);
        const float2 gn0 = *(const float2*)(p0 + 512);
        const float2 gr1 = *(const float2*)(p1);
        const float2 gz1 = *(const float2*)(p1 + 256);
        const float2 gn1 = *(const float2*)(p1 + 512);

        // ---- phase A: D = h @ W^T (3 bf16 chains) ----
        float a0[4] = {0.f, 0.f, 0.f, 0.f};
        float a1[4] = {0.f, 0.f, 0.f, 0.f};
        float a2[4] = {0.f, 0.f, 0.f, 0.f};
#pragma unroll
        for (int ks = 0; ks < 16; ks++) {
            const uint32_t ko = (uint32_t)(ks * 32);
            uint32_t ah[4], al[4];
            ldsm_x4(ah, aHi + ko);
            ldsm_x4(al, aLo + ko);
            uint32_t bh0[2], bh1[2], bh2[2], bl0[2], bl1[2], bl2[2];
            ldsm_x2(bh0, bAd[0] + ko);
            ldsm_x2(bh1, bAd[1] + ko);
            ldsm_x2(bh2, bAd[2] + ko);
            ldsm_x2(bl0, bAd[0] + WLO_B + ko);
            ldsm_x2(bl1, bAd[1] + WLO_B + ko);
            ldsm_x2(bl2, bAd[2] + WLO_B + ko);
            mma_bf16(a0, ah, bh0); mma_bf16(a1, ah, bh1); mma_bf16(a2, ah, bh2);
            mma_bf16(a0, ah, bl0); mma_bf16(a1, ah, bl1); mma_bf16(a2, ah, bl2);
            mma_bf16(a0, al, bh0); mma_bf16(a1, al, bh1); mma_bf16(a2, al, bh2);
        }
        // stage D fragments
        {
            const int col = tn0 * 8 + qc;
            *(float2*)(Dm + grp * DSTR + col)            = make_float2(a0[0], a0[1]);
            *(float2*)(Dm + (grp + 8) * DSTR + col)      = make_float2(a0[2], a0[3]);
            *(float2*)(Dm + grp * DSTR + col + 8)        = make_float2(a1[0], a1[1]);
            *(float2*)(Dm + (grp + 8) * DSTR + col + 8)  = make_float2(a1[2], a1[3]);
            *(float2*)(Dm + grp * DSTR + col + 16)       = make_float2(a2[0], a2[1]);
            *(float2*)(Dm + (grp + 8) * DSTR + col + 16) = make_float2(a2[2], a2[3]);
        }
        cluster_sync_();   // D visible; all ranks done reading h

        // ---- phase B: GRU cells + cluster-wide h update ----
        {
            const float2 dr0 = *(const float2*)(Dm + row0 * DSTR + lu);
            const float2 dz0 = *(const float2*)(Dm + row0 * DSTR + 64 + lu);
            const float2 dn0 = *(const float2*)(Dm + row0 * DSTR + 128 + lu);
            const float2 dr1 = *(const float2*)(Dm + (row0 + 1) * DSTR + lu);
            const float2 dz1 = *(const float2*)(Dm + (row0 + 1) * DSTR + 64 + lu);
            const float2 dn1 = *(const float2*)(Dm + (row0 + 1) * DSTR + 128 + lu);

            const float h00 = gru_cell(gr0.x, gz0.x, gn0.x, dr0.x, dz0.x, dn0.x, bnv.x, hp0.x);
            const float h01 = gru_cell(gr0.y, gz0.y, gn0.y, dr0.y, dz0.y, dn0.y, bnv.y, hp0.y);
            const float h10 = gru_cell(gr1.x, gz1.x, gn1.x, dr1.x, dz1.x, dn1.x, bnv.x, hp1.x);
            const float h11 = gru_cell(gr1.y, gz1.y, gn1.y, dr1.y, dz1.y, dn1.y, bnv.y, hp1.y);
            hp0 = make_float2(h00, h01);
            hp1 = make_float2(h10, h11);

            __nv_bfloat162 hi0 = __floats2bfloat162_rn(h00, h01);
            __nv_bfloat162 lo0 = __floats2bfloat162_rn(h00 - __bfloat162float(hi0.x),
                                                       h01 - __bfloat162float(hi0.y));
            __nv_bfloat162 hi1 = __floats2bfloat162_rn(h10, h11);
            __nv_bfloat162 lo1 = __floats2bfloat162_rn(h10 - __bfloat162float(hi1.x),
                                                       h11 - __bfloat162float(hi1.y));
            const uint32_t wh0 = *reinterpret_cast<uint32_t*>(&hi0);
            const uint32_t wl0 = *reinterpret_cast<uint32_t*>(&lo0);
            const uint32_t wh1 = *reinterpret_cast<uint32_t*>(&hi1);
            const uint32_t wl1 = *reinterpret_cast<uint32_t*>(&lo1);
#pragma unroll
            for (int r = 0; r < 4; r++) {
                stc_b32(pp[r] + offH0, wh0);
                stc_b32(pp[r] + offH0 + (HLO_B - HHI_B), wl0);
                stc_b32(pp[r] + offH1, wh1);
                stc_b32(pp[r] + offH1 + (HLO_B - HHI_B), wl1);
            }
        }
        cluster_sync_();   // h_{t+1} visible everywhere
    }

    // final h (in registers) -> g_hfin
    *(float2*)(g_hfin + (size_t)(cl * 16 + row0) * H_ + gu)     = hp0;
    *(float2*)(g_hfin + (size_t)(cl * 16 + row0 + 1) * H_ + gu) = hp1;
}

// ---------------------------------------------------------------------------
// Phase 3: out = h_final @ w_lin^T + bias_out   (512 x 128, trivial)
// ---------------------------------------------------------------------------
__global__ void __launch_bounds__(128) k_out(const float* __restrict__ wl,
                                             const float* __restrict__ bo,
                                             float* __restrict__ out)
{
    __shared__ float sh[256];
    const int b = blockIdx.x, o = threadIdx.x;
    sh[o]       = g_hfin[(size_t)b * H_ + o];
    sh[o + 128] = g_hfin[(size_t)b * H_ + o + 128];
    __syncthreads();

    float acc = bo[o];
    const float4* wp = (const float4*)(wl + (size_t)o * H_);
#pragma unroll 8
    for (int q = 0; q < 64; q++) {
        const float4 w = wp[q];
        const float4 h = *(const float4*)(sh + q * 4);
        acc += w.x * h.x + w.y * h.y + w.z * h.z + w.w * h.w;
    }
    out[(size_t)b * OUT_ + o] = acc;
}

// ---------------------------------------------------------------------------
extern "C" void kernel_launch(void* const* d_in, const int* in_sizes, int n_in,
                              void* d_out, int out_size)
{
    (void)in_sizes; (void)n_in; (void)out_size;
    const float* x   = (const float*)d_in[0];  // (B,T,IN)
    const float* wih = (const float*)d_in[1];  // (3H,IN)
    const float* whh = (const float*)d_in[2];  // (3H,H)
    const float* bg  = (const float*)d_in[3];  // (3H)
    const float* bnn = (const float*)d_in[4];  // (H)
    const float* wl  = (const float*)d_in[5];  // (OUT,H)
    const float* bo  = (const float*)d_in[6];  // (OUT)
    float* out = (float*)d_out;                // (B,OUT)

    cudaFuncSetAttribute(k_ih_mma,  cudaFuncAttributeMaxDynamicSharedMemorySize, P1_SMEM_BYTES);
    cudaFuncSetAttribute(k_rec_mma, cudaFuncAttributeMaxDynamicSharedMemorySize, KR_SMEM_BYTES);

    k_ih_mma<<<dim3(G3_ / 64, (B_ * T_) / 128), 256, P1_SMEM_BYTES>>>(x, wih, bg);
    k_rec_mma<<<128, 256, KR_SMEM_BYTES>>>(whh, bnn);
    k_out<<<B_, 128>>>(wl, bo, out);
}